// round 5
// baseline (speedup 1.0000x reference)
#include <cuda_runtime.h>

#define HALFW 6
#define MAXC  63
#define NK    21
#define NB    64
#define NC    256
#define NH    64
#define NW    64
#define HW    (NH * NW)

// Scratch (allocation-free rule: __device__ globals; zero-initialized)
__device__ float g_fm[2][NB][NH][NW];   // channel means, 2 MiB
__device__ float g_bm[2][NK][NB];       // per-box means
__device__ int   g_sync[2][NB];         // per-(t,b) completion (self-resetting)
__device__ int   g_done = 0;            // grid completion (self-resetting)

// ---------------------------------------------------------------------------
// Single fused kernel.
// grid = (4, 64, 2), block = 256. Main loop is bit-identical to the proven
// 80us channel-mean. Epilogue: 4th block done per (t,b) computes that
// batch's 21 boxes; 128th finisher computes the MSE. No second launch.
// ---------------------------------------------------------------------------
__global__ void __launch_bounds__(256) fused_kernel(
    const float* __restrict__ f1, const float* __restrict__ f2,
    const int* __restrict__ pre1, const int* __restrict__ pre2,
    float* __restrict__ out)
{
    const int t    = blockIdx.z;
    const int b    = blockIdx.y;
    const int tid  = threadIdx.x;
    const int hw4  = blockIdx.x * blockDim.x + tid;          // 0..1023

    // ---------------- proven channel-mean loop (unchanged) ----------------
    const float4* __restrict__ f4 =
        reinterpret_cast<const float4*>(t == 0 ? f1 : f2);
    const float4* __restrict__ p = f4 + (size_t)b * NC * (HW / 4) + hw4;

    float4 acc = make_float4(0.f, 0.f, 0.f, 0.f);
#pragma unroll 8
    for (int c = 0; c < NC; ++c) {
        float4 v = p[(size_t)c * (HW / 4)];
        acc.x += v.x; acc.y += v.y; acc.z += v.z; acc.w += v.w;
    }
    const float sc = 1.0f / (float)NC;
    float4 o = make_float4(acc.x * sc, acc.y * sc, acc.z * sc, acc.w * sc);
    reinterpret_cast<float4*>(&g_fm[t][b][0][0])[hw4] = o;

    // ---------------- per-(t,b) completion handoff ----------------
    const int warp = tid >> 5;
    const int lane = tid & 31;
    __shared__ int s_role;

    __threadfence();               // each thread orders its g_fm stores
    __syncthreads();
    if (tid == 0)
        s_role = (atomicAdd(&g_sync[t][b], 1) == 3) ? 1 : 0;
    __syncthreads();
    if (!s_role) return;

    if (tid == 0) g_sync[t][b] = 0;           // reset for next replay
    __threadfence();                          // acquire: see all 4 tiles

    // ---------------- 21 boxes for this (t,b): warp-per-keypoint ----------
    const int* __restrict__ pre = (t == 0) ? pre1 : pre2;
    const float* __restrict__ fm = &g_fm[t][b][0][0];

    for (int k = warp; k < NK; k += 8) {
        const int x = pre[(b * NK + k) * 2 + 0];
        const int y = pre[(b * NK + k) * 2 + 1];
        // x masks rows (H), y masks cols (W); exclusive upper bounds.
        const int left  = max(x - HALFW, 0);
        const int right = min(x + HALFW, MAXC);
        const int down  = max(y - HALFW, 0);
        const int up    = min(y + HALFW, MAXC);
        const int nh = right - left;          // 6..12
        const int nw = up - down;             // 6..12
        const float inv_cnt = 1.0f / (float)(nh * nw);

        float s = 0.f;
#pragma unroll
        for (int it = 0; it < 5; ++it) {
            const int idx = lane + 32 * it;   // 0..159
            const int r = idx / 12;           // constant divisor -> mul/shift
            const int c = idx - r * 12;
            if ((idx < 144) && (r < nh) && (c < nw))
                s += __ldcg(&fm[(left + r) * NW + (down + c)]);
        }
#pragma unroll
        for (int off = 16; off > 0; off >>= 1)
            s += __shfl_down_sync(0xffffffffu, s, off);
        if (lane == 0)
            g_bm[t][k][b] = s * inv_cnt;      // each slot written once
    }

    // ---------------- grid completion: last of 128 finishers --------------
    __shared__ int s_last;
    __syncthreads();
    if (tid == 0) {
        __threadfence();
        s_last = (atomicAdd(&g_done, 1) == 2 * NB - 1) ? 1 : 0;
    }
    __syncthreads();
    if (!s_last) return;

    __threadfence();
    __shared__ float s_fea[2 * NK];
    for (int g = warp; g < 2 * NK; g += 8) {
        const int tt = g / NK;
        const int kk = g - tt * NK;
        float v = __ldcg(&g_bm[tt][kk][lane]) + __ldcg(&g_bm[tt][kk][lane + 32]);
#pragma unroll
        for (int off = 16; off > 0; off >>= 1)
            v += __shfl_down_sync(0xffffffffu, v, off);
        if (lane == 0)
            s_fea[g] = v * (1.0f / (float)NB);
    }
    __syncthreads();
    if (tid == 0) {
        float acc2 = 0.f;
#pragma unroll
        for (int kk = 0; kk < NK; ++kk) {
            const float d = s_fea[kk] - 0.999f * s_fea[NK + kk];
            acc2 += d * d;
        }
        out[0] = acc2 * (1.0f / (float)NK);
        g_done = 0;                           // reset for next replay
    }
}

extern "C" void kernel_launch(void* const* d_in, const int* in_sizes, int n_in,
                              void* d_out, int out_size)
{
    const float* f1   = (const float*)d_in[0];
    const float* f2   = (const float*)d_in[1];
    const int*   pre1 = (const int*)d_in[2];
    const int*   pre2 = (const int*)d_in[3];

    fused_kernel<<<dim3(HW / (256 * 4), NB, 2), 256>>>(
        f1, f2, pre1, pre2, (float*)d_out);
}

// round 6
// speedup vs baseline: 1.0033x; 1.0033x over previous
#include <cuda_runtime.h>

#define HALFW 6
#define MAXC  63
#define NK    21
#define NB    64
#define NC    256
#define NH    64
#define NW    64
#define HW    (NH * NW)

// Scratch (allocation-free rule: __device__ globals; zero-initialized)
__device__ float g_fm[2][NB][NH][NW];   // channel means (only needed cells written)
__device__ float g_bm[2][NK][NB];       // per-box means
__device__ int   g_sync[2][NB];         // per-(t,b) completion (self-resetting)
__device__ int   g_done = 0;            // grid completion (self-resetting)

// ---------------------------------------------------------------------------
// Single fused kernel, sparse read version.
// grid = (4, 64, 2), block = 256.
// Phase 0: build compact list of float4 positions needed by this (t,b)'s
//          21 boxes (union coverage ~55%) -> skip ~45% of DRAM reads.
// Phase 1: channel-reduce only listed positions (same loop shape as the
//          proven 80us kernel; unroll 8, float4).
// Phase 2: R5 epilogue unchanged: 4th block per (t,b) does the 21 boxes,
//          128th finisher does the MSE.
// ---------------------------------------------------------------------------
__global__ void __launch_bounds__(256) fused_sparse_kernel(
    const float* __restrict__ f1, const float* __restrict__ f2,
    const int* __restrict__ pre1, const int* __restrict__ pre2,
    float* __restrict__ out)
{
    const int t   = blockIdx.z;
    const int b   = blockIdx.y;
    const int tid = threadIdx.x;

    __shared__ int            s_pre[2 * NK];
    __shared__ unsigned       s_rowmask[NH];
    __shared__ int            s_rowoff[NH];
    __shared__ unsigned short s_list[HW / 4];   // needed hw4 positions, sorted
    __shared__ int            s_n;

    const int* __restrict__ pre = (t == 0) ? pre1 : pre2;
    if (tid < 2 * NK) s_pre[tid] = pre[b * 2 * NK + tid];
    __syncthreads();

    // ---- Phase 0: per-row needed-float4 masks, then compact list ----
    if (tid < NH) {
        const int h = tid;
        unsigned m = 0;
#pragma unroll
        for (int k = 0; k < NK; ++k) {
            const int x = s_pre[2 * k + 0];
            const int y = s_pre[2 * k + 1];
            const int left  = max(x - HALFW, 0);
            const int right = min(x + HALFW, MAXC);    // exclusive
            if (h >= left && h < right) {
                const int down = max(y - HALFW, 0);
                const int up   = min(y + HALFW, MAXC); // exclusive
                const int a  = down >> 2;
                const int bq = (up - 1) >> 2;          // inclusive float4 idx
                m |= ((1u << (bq - a + 1)) - 1u) << a;
            }
        }
        s_rowmask[h] = m;
    }
    __syncthreads();
    if (tid == 0) {
        int off = 0;
#pragma unroll
        for (int h = 0; h < NH; ++h) { s_rowoff[h] = off; off += __popc(s_rowmask[h]); }
        s_n = off;
    }
    __syncthreads();
    if (tid < NH) {
        const int h = tid;
        unsigned m = s_rowmask[h];
        int off = s_rowoff[h];
        while (m) {
            const int w4 = __ffs(m) - 1;
            m &= m - 1;
            s_list[off++] = (unsigned short)(h * 16 + w4);
        }
    }
    __syncthreads();

    // ---- Phase 1: channel reduce, needed positions only ----
    const int n  = s_n;
    const int li = blockIdx.x * 256 + tid;
    if (li < n) {
        const int hw4 = s_list[li];
        const float4* __restrict__ f4 =
            reinterpret_cast<const float4*>(t == 0 ? f1 : f2);
        const float4* __restrict__ p = f4 + (size_t)b * NC * (HW / 4) + hw4;

        float4 acc = make_float4(0.f, 0.f, 0.f, 0.f);
#pragma unroll 8
        for (int c = 0; c < NC; ++c) {
            float4 v = p[(size_t)c * (HW / 4)];
            acc.x += v.x; acc.y += v.y; acc.z += v.z; acc.w += v.w;
        }
        const float sc = 1.0f / (float)NC;
        float4 o = make_float4(acc.x * sc, acc.y * sc, acc.z * sc, acc.w * sc);
        reinterpret_cast<float4*>(&g_fm[t][b][0][0])[hw4] = o;
    }

    // ---- Phase 2: per-(t,b) completion handoff (all 4 blocks arrive) ----
    const int warp = tid >> 5;
    const int lane = tid & 31;
    __shared__ int s_role;

    __threadfence();
    __syncthreads();
    if (tid == 0)
        s_role = (atomicAdd(&g_sync[t][b], 1) == 3) ? 1 : 0;
    __syncthreads();
    if (!s_role) return;

    if (tid == 0) g_sync[t][b] = 0;           // reset for next replay
    __threadfence();                          // acquire: see all 4 slices

    // 21 boxes for this (t,b): warp-per-keypoint, div-free predicated 12x12
    const float* __restrict__ fm = &g_fm[t][b][0][0];
    for (int k = warp; k < NK; k += 8) {
        const int x = s_pre[2 * k + 0];
        const int y = s_pre[2 * k + 1];
        const int left  = max(x - HALFW, 0);
        const int right = min(x + HALFW, MAXC);
        const int down  = max(y - HALFW, 0);
        const int up    = min(y + HALFW, MAXC);
        const int nh = right - left;          // 6..12
        const int nw = up - down;             // 6..12
        const float inv_cnt = 1.0f / (float)(nh * nw);

        float s = 0.f;
#pragma unroll
        for (int it = 0; it < 5; ++it) {
            const int idx = lane + 32 * it;   // 0..159
            const int r = idx / 12;           // constant divisor -> mul/shift
            const int c = idx - r * 12;
            if ((idx < 144) && (r < nh) && (c < nw))
                s += __ldcg(&fm[(left + r) * NW + (down + c)]);
        }
#pragma unroll
        for (int off = 16; off > 0; off >>= 1)
            s += __shfl_down_sync(0xffffffffu, s, off);
        if (lane == 0)
            g_bm[t][k][b] = s * inv_cnt;      // each slot written once
    }

    // ---- grid completion: last of 128 finishers computes the MSE ----
    __shared__ int s_last;
    __syncthreads();
    if (tid == 0) {
        __threadfence();
        s_last = (atomicAdd(&g_done, 1) == 2 * NB - 1) ? 1 : 0;
    }
    __syncthreads();
    if (!s_last) return;

    __threadfence();
    __shared__ float s_fea[2 * NK];
    for (int g = warp; g < 2 * NK; g += 8) {
        const int tt = g / NK;
        const int kk = g - tt * NK;
        float v = __ldcg(&g_bm[tt][kk][lane]) + __ldcg(&g_bm[tt][kk][lane + 32]);
#pragma unroll
        for (int off = 16; off > 0; off >>= 1)
            v += __shfl_down_sync(0xffffffffu, v, off);
        if (lane == 0)
            s_fea[g] = v * (1.0f / (float)NB);
    }
    __syncthreads();
    if (tid == 0) {
        float acc2 = 0.f;
#pragma unroll
        for (int kk = 0; kk < NK; ++kk) {
            const float d = s_fea[kk] - 0.999f * s_fea[NK + kk];
            acc2 += d * d;
        }
        out[0] = acc2 * (1.0f / (float)NK);
        g_done = 0;                           // reset for next replay
    }
}

extern "C" void kernel_launch(void* const* d_in, const int* in_sizes, int n_in,
                              void* d_out, int out_size)
{
    const float* f1   = (const float*)d_in[0];
    const float* f2   = (const float*)d_in[1];
    const int*   pre1 = (const int*)d_in[2];
    const int*   pre2 = (const int*)d_in[3];

    fused_sparse_kernel<<<dim3(HW / (256 * 4), NB, 2), 256>>>(
        f1, f2, pre1, pre2, (float*)d_out);
}

// round 8
// speedup vs baseline: 1.0487x; 1.0453x over previous
#include <cuda_runtime.h>

#define HALFW 6
#define MAXC  63
#define NK    21
#define NB    64
#define NC    256
#define NH    64
#define NW    64
#define HW    (NH * NW)
#define NBLK  512                 // (4, 64, 2)

// Scratch (allocation-free rule: __device__ globals; zero-initialized)
__device__ float g_part[2][NB][4][NK];  // per-block raw box partial sums
__device__ int   g_done = 0;            // grid completion counter (self-resetting)

// ---------------------------------------------------------------------------
// Single fused kernel. grid = (4, 64, 2), block = 256.
//  - warp0 builds a 32-bit mask of needed 128B lines (16 rows x 2 half-rows)
//  - threads channel-reduce only needed lines (~93% avg) -- proven loop shape
//  - fm tile staged in smem (16B-aligned!); no g_fm global round-trip
//  - per-block 21 box partials -> g_part (21 floats/block before the fence)
//  - last of 512 blocks reduces g_part + computes MSE
// ---------------------------------------------------------------------------
__global__ void __launch_bounds__(256) fused_kernel(
    const float* __restrict__ f1, const float* __restrict__ f2,
    const int* __restrict__ pre1, const int* __restrict__ pre2,
    float* __restrict__ out)
{
    const int t   = blockIdx.z;
    const int b   = blockIdx.y;
    const int tid = threadIdx.x;
    const int h0  = blockIdx.x * 16;          // this block's row base

    __shared__ __align__(16) float s_fm[16 * NW];  // fm tile (chan-mean), 4KB
    __shared__ int      s_pre[2 * NK];
    __shared__ unsigned s_mask;

    const int* __restrict__ pre = (t == 0) ? pre1 : pre2;
    if (tid < 2 * NK) s_pre[tid] = pre[b * 2 * NK + tid];
    __syncthreads();

    // ---- needed-line mask: line L = (row h0+(L>>1), half (L&1)) ----
    if (tid < 32) {
        const int h  = h0 + (tid >> 1);
        const int c0 = (tid & 1) * 32;        // half-row col base
        bool need = false;
#pragma unroll
        for (int k = 0; k < NK; ++k) {
            const int x = s_pre[2 * k + 0];
            const int y = s_pre[2 * k + 1];
            const int left  = max(x - HALFW, 0);
            const int right = min(x + HALFW, MAXC);   // exclusive
            const int down  = max(y - HALFW, 0);
            const int up    = min(y + HALFW, MAXC);   // exclusive
            need |= (h >= left) & (h < right) & (down < c0 + 32) & (up > c0);
        }
        const unsigned m = __ballot_sync(0xffffffffu, need);
        if (tid == 0) s_mask = m;
    }
    __syncthreads();

    const unsigned mask = s_mask;
    const int nlines    = __popc(mask);
    const int j         = tid >> 3;           // line slot 0..31
    const int f         = tid & 7;            // float4 within 128B line

    // ---- channel reduce over needed lines only (proven loop shape) ----
    if (j < nlines) {
        const int line = __fns(mask, 0, j + 1);   // (j+1)-th set bit
        const int lr = line >> 1;
        const int c4 = (line & 1) * 8 + f;        // float4 col 0..15
        const int hw4 = (h0 + lr) * 16 + c4;

        const float4* __restrict__ f4 =
            reinterpret_cast<const float4*>(t == 0 ? f1 : f2);
        const float4* __restrict__ p = f4 + (size_t)b * NC * (HW / 4) + hw4;

        float4 acc = make_float4(0.f, 0.f, 0.f, 0.f);
#pragma unroll 8
        for (int c = 0; c < NC; ++c) {
            float4 v = p[(size_t)c * (HW / 4)];
            acc.x += v.x; acc.y += v.y; acc.z += v.z; acc.w += v.w;
        }
        const float sc = 1.0f / (float)NC;
        float4 o = make_float4(acc.x * sc, acc.y * sc, acc.z * sc, acc.w * sc);
        *reinterpret_cast<float4*>(&s_fm[lr * NW + c4 * 4]) = o;
    }
    __syncthreads();

    // ---- per-block box partials: warp-per-keypoint, div-free 12x12 ----
    const int warp = tid >> 5;
    const int lane = tid & 31;
    for (int k = warp; k < NK; k += 8) {
        const int x = s_pre[2 * k + 0];
        const int y = s_pre[2 * k + 1];
        const int left  = max(x - HALFW, 0);
        const int right = min(x + HALFW, MAXC);
        const int down  = max(y - HALFW, 0);
        const int up    = min(y + HALFW, MAXC);
        const int rl = max(left, h0);
        const int rr = min(right, h0 + 16);
        const int nhl = rr - rl;              // may be <= 0
        const int nw  = up - down;            // 6..12

        float s = 0.f;
#pragma unroll
        for (int it = 0; it < 5; ++it) {
            const int idx = lane + 32 * it;   // 0..159
            const int r = idx / 12;           // constant divisor -> mul/shift
            const int c = idx - r * 12;
            if ((idx < 144) && (r < nhl) && (c < nw))
                s += s_fm[(rl - h0 + r) * NW + (down + c)];
        }
#pragma unroll
        for (int off = 16; off > 0; off >>= 1)
            s += __shfl_down_sync(0xffffffffu, s, off);
        if (lane == 0)
            g_part[t][b][blockIdx.x][k] = s;  // every slot written each call
    }

    // ---- grid completion: last of 512 blocks finishes ----
    __shared__ int s_last;
    __threadfence();
    __syncthreads();
    if (tid == 0)
        s_last = (atomicAdd(&g_done, 1) == NBLK - 1) ? 1 : 0;
    __syncthreads();
    if (!s_last) return;

    __threadfence();
    __shared__ float s_fea[2 * NK];
    for (int g = warp; g < 2 * NK; g += 8) {
        const int tt = g / NK;
        const int kk = g - tt * NK;
        const int* __restrict__ pp = (tt == 0) ? pre1 : pre2;
        float v = 0.f;
#pragma unroll
        for (int half = 0; half < 2; ++half) {
            const int bb = lane + 32 * half;
            const int x = pp[(bb * NK + kk) * 2 + 0];
            const int y = pp[(bb * NK + kk) * 2 + 1];
            const int cnt = (min(x + HALFW, MAXC) - max(x - HALFW, 0)) *
                            (min(y + HALFW, MAXC) - max(y - HALFW, 0));
            float ssum = 0.f;
#pragma unroll
            for (int xb = 0; xb < 4; ++xb)
                ssum += __ldcg(&g_part[tt][bb][xb][kk]);
            v += ssum * (1.0f / (float)cnt);
        }
#pragma unroll
        for (int off = 16; off > 0; off >>= 1)
            v += __shfl_down_sync(0xffffffffu, v, off);
        if (lane == 0)
            s_fea[g] = v * (1.0f / (float)NB);
    }
    __syncthreads();
    if (tid == 0) {
        float acc2 = 0.f;
#pragma unroll
        for (int kk = 0; kk < NK; ++kk) {
            const float d = s_fea[kk] - 0.999f * s_fea[NK + kk];
            acc2 += d * d;
        }
        out[0] = acc2 * (1.0f / (float)NK);
        g_done = 0;                           // reset for next replay
    }
}

extern "C" void kernel_launch(void* const* d_in, const int* in_sizes, int n_in,
                              void* d_out, int out_size)
{
    const float* f1   = (const float*)d_in[0];
    const float* f2   = (const float*)d_in[1];
    const int*   pre1 = (const int*)d_in[2];
    const int*   pre2 = (const int*)d_in[3];

    fused_kernel<<<dim3(4, NB, 2), 256>>>(f1, f2, pre1, pre2, (float*)d_out);
}